// round 15
// baseline (speedup 1.0000x reference)
#include <cuda_runtime.h>
#include <cuda_bf16.h>
#include <cstdint>

#define NN 50000
#define NE 600000
#define DD 128
#define NB1 ((NN + 255) / 256)     // 196 scan blocks

// ---------------- device scratch ----------------
__device__ __align__(16) __nv_bfloat16 g_y1lb[NN * DD];  // X @ W1_l (bf16, gathered)
__device__ __align__(16) float g_y1r[NN * DD];           // X @ W1_r (fp32, self term)
__device__ __align__(16) __nv_bfloat16 g_wbh[2 * DD * DD];  // W^T hi, [mat][n][k]
__device__ __align__(16) __nv_bfloat16 g_wbl[2 * DD * DD];  // W^T lo
__device__ __align__(16) float g_s[NN];          // h . W2_l
__device__ __align__(16) float g_t[NN];          // h . W2_r
__device__ __align__(16) int   g_deg[NN];
__device__ __align__(16) int   g_fill[NN];
__device__ __align__(16) int   g_incl[NN];
__device__ __align__(16) int   g_bsum[256];
__device__ __align__(16) int   g_off[NN + 2];
__device__ __align__(16) int   g_srcs[NE];

__device__ __forceinline__ int clampi(int v, int lo, int hi) {
    return v < lo ? lo : (v > hi ? hi : v);
}
__device__ __forceinline__ void mma_bf16(float* c, const uint32_t* a,
                                         uint32_t b0, uint32_t b1) {
    asm volatile(
        "mma.sync.aligned.m16n8k16.row.col.f32.bf16.bf16.f32 "
        "{%0,%1,%2,%3}, {%4,%5,%6,%7}, {%8,%9}, {%0,%1,%2,%3};"
        : "+f"(c[0]), "+f"(c[1]), "+f"(c[2]), "+f"(c[3])
        : "r"(a[0]), "r"(a[1]), "r"(a[2]), "r"(a[3]), "r"(b0), "r"(b1));
}

// ---------------- W hi/lo split + transpose: [k][n] -> [n][k] bf16 ----------
__global__ void conv_w_kernel(const float* __restrict__ Wl,
                              const float* __restrict__ Wr) {
    int i = blockIdx.x * blockDim.x + threadIdx.x;
    if (i >= DD * DD) return;
    int k = i >> 7, n = i & 127;
    float a = Wl[i], b = Wr[i];
    __nv_bfloat16 ah = __float2bfloat16_rn(a);
    __nv_bfloat16 bh = __float2bfloat16_rn(b);
    g_wbh[n * DD + k] = ah;
    g_wbl[n * DD + k] = __float2bfloat16_rn(a - __bfloat162float(ah));
    g_wbh[DD * DD + n * DD + k] = bh;
    g_wbl[DD * DD + n * DD + k] = __float2bfloat16_rn(b - __bfloat162float(bh));
}

// ---------------- CSR build ----------------
__global__ void zero_kernel() {
    int i = blockIdx.x * blockDim.x + threadIdx.x;
    if (i < NN) { g_deg[i] = 0; g_fill[i] = 0; }
}

__global__ void count_kernel(const int* __restrict__ ei) {
    int i = blockIdx.x * blockDim.x + threadIdx.x;
    if (i < NE / 4) {
        int4 d = ((const int4*)(ei + NE))[i];
        atomicAdd(&g_deg[clampi(d.x, 0, NN - 1)], 1);
        atomicAdd(&g_deg[clampi(d.y, 0, NN - 1)], 1);
        atomicAdd(&g_deg[clampi(d.z, 0, NN - 1)], 1);
        atomicAdd(&g_deg[clampi(d.w, 0, NN - 1)], 1);
    }
}

__global__ void scan1_kernel() {
    __shared__ int sh[256];
    int b = blockIdx.x, t = threadIdx.x, i = b * 256 + t;
    int v = (i < NN) ? g_deg[i] : 0;
    sh[t] = v;
    __syncthreads();
    #pragma unroll
    for (int ofs = 1; ofs < 256; ofs <<= 1) {
        int idx = (t >= ofs) ? (t - ofs) : t;
        int u = sh[idx];
        __syncthreads();
        if (t >= ofs) sh[t] += u;
        __syncthreads();
    }
    if (i < NN) g_incl[i] = sh[t];
    if (t == 255) g_bsum[b] = sh[255];
}

__global__ void scan23_kernel() {
    __shared__ int sh[256];
    int b = blockIdx.x, t = threadIdx.x;
    sh[t] = (t < b) ? g_bsum[t] : 0;
    __syncthreads();
    #pragma unroll
    for (int ofs = 128; ofs; ofs >>= 1) {
        if (t < ofs) sh[t] += sh[t + ofs];
        __syncthreads();
    }
    int boff = sh[0];
    int i = b * 256 + t;
    if (i < NN) g_off[i + 1] = g_incl[i] + boff;
    if (i == 0) g_off[0] = 0;
}

__global__ void fill_kernel(const int* __restrict__ ei) {
    int i = blockIdx.x * blockDim.x + threadIdx.x;
    if (i < NE / 4) {
        int4 s4 = ((const int4*)ei)[i];
        int4 d4 = ((const int4*)(ei + NE))[i];
        {
            int d = clampi(d4.x, 0, NN - 1);
            int pos = clampi(g_off[d] + atomicAdd(&g_fill[d], 1), 0, NE - 1);
            g_srcs[pos] = clampi(s4.x, 0, NN - 1);
        }
        {
            int d = clampi(d4.y, 0, NN - 1);
            int pos = clampi(g_off[d] + atomicAdd(&g_fill[d], 1), 0, NE - 1);
            g_srcs[pos] = clampi(s4.y, 0, NN - 1);
        }
        {
            int d = clampi(d4.z, 0, NN - 1);
            int pos = clampi(g_off[d] + atomicAdd(&g_fill[d], 1), 0, NE - 1);
            g_srcs[pos] = clampi(s4.z, 0, NN - 1);
        }
        {
            int d = clampi(d4.w, 0, NN - 1);
            int pos = clampi(g_off[d] + atomicAdd(&g_fill[d], 1), 0, NE - 1);
            g_srcs[pos] = clampi(s4.w, 0, NN - 1);
        }
    }
}

// ---------------- tensor-core GEMM (bf16 3-term split, fused conversion) ---
// Exactly the R9 best-measured version: in-register A cvt, int4 B staging,
// k-chunk 32, 8 warps of 32x64, m16n8k16. D = Xh*Wh + Xh*Wl + Xl*Wh.
#define APAD 40   // bf16 elems per row (32 + 8 pad) = 80 B
__global__ void __launch_bounds__(256, 2)
gemm_tc_kernel(const float* __restrict__ X) {
    __shared__ __nv_bfloat16 Ah[128][APAD], Al[128][APAD];
    __shared__ __nv_bfloat16 Bh[128][APAD], Bl[128][APAD];   // [col][k]

    const __nv_bfloat16* Wh = g_wbh + blockIdx.y * DD * DD;
    const __nv_bfloat16* Wl = g_wbl + blockIdx.y * DD * DD;

    int row0 = blockIdx.x * 128;
    int t = threadIdx.x, w = t >> 5, lane = t & 31;
    int wm = w & 3, wn = w >> 2;
    int lq = lane >> 2, lr = lane & 3;

    float c[2][8][4];
    #pragma unroll
    for (int m = 0; m < 2; m++)
        #pragma unroll
        for (int n = 0; n < 8; n++)
            #pragma unroll
            for (int j = 0; j < 4; j++) c[m][n][j] = 0.f;

    for (int kc = 0; kc < DD; kc += 32) {
        // stage A: 128 rows x 32 k; convert fp32 -> bf16 hi/lo in-register
        #pragma unroll
        for (int l = 0; l < 4; l++) {
            int s = t + 256 * l;                 // 0..1023 float4 slots
            int r = s >> 3, c4 = s & 7;
            int gr = row0 + r; gr = gr < NN ? gr : NN - 1;
            float4 v = *(const float4*)&X[gr * DD + kc + c4 * 4];
            __nv_bfloat16 hx = __float2bfloat16_rn(v.x);
            __nv_bfloat16 hy = __float2bfloat16_rn(v.y);
            __nv_bfloat16 hz = __float2bfloat16_rn(v.z);
            __nv_bfloat16 hw = __float2bfloat16_rn(v.w);
            Ah[r][c4 * 4 + 0] = hx; Ah[r][c4 * 4 + 1] = hy;
            Ah[r][c4 * 4 + 2] = hz; Ah[r][c4 * 4 + 3] = hw;
            Al[r][c4 * 4 + 0] = __float2bfloat16_rn(v.x - __bfloat162float(hx));
            Al[r][c4 * 4 + 1] = __float2bfloat16_rn(v.y - __bfloat162float(hy));
            Al[r][c4 * 4 + 2] = __float2bfloat16_rn(v.z - __bfloat162float(hz));
            Al[r][c4 * 4 + 3] = __float2bfloat16_rn(v.w - __bfloat162float(hw));
        }
        // stage B: pre-converted [col][k] bf16, pure int4 copy of k-slice
        #pragma unroll
        for (int l = 0; l < 2; l++) {
            int s = t + 256 * l;                 // 0..511 int4 slots
            int col = s >> 2, q = s & 3;
            *(int4*)&Bh[col][q * 8] = *(const int4*)&Wh[col * DD + kc + q * 8];
            *(int4*)&Bl[col][q * 8] = *(const int4*)&Wl[col * DD + kc + q * 8];
        }
        __syncthreads();

        #pragma unroll
        for (int k0 = 0; k0 < 32; k0 += 16) {
            uint32_t ah[2][4], al[2][4];
            #pragma unroll
            for (int m = 0; m < 2; m++) {
                int r = wm * 32 + m * 16 + lq;
                int kk = k0 + 2 * lr;
                ah[m][0] = *(const uint32_t*)&Ah[r][kk];
                ah[m][1] = *(const uint32_t*)&Ah[r + 8][kk];
                ah[m][2] = *(const uint32_t*)&Ah[r][kk + 8];
                ah[m][3] = *(const uint32_t*)&Ah[r + 8][kk + 8];
                al[m][0] = *(const uint32_t*)&Al[r][kk];
                al[m][1] = *(const uint32_t*)&Al[r + 8][kk];
                al[m][2] = *(const uint32_t*)&Al[r][kk + 8];
                al[m][3] = *(const uint32_t*)&Al[r + 8][kk + 8];
            }
            #pragma unroll
            for (int n = 0; n < 8; n++) {
                int col = wn * 64 + n * 8 + lq;
                int kk = k0 + 2 * lr;
                uint32_t bh0 = *(const uint32_t*)&Bh[col][kk];
                uint32_t bh1 = *(const uint32_t*)&Bh[col][kk + 8];
                uint32_t bl0 = *(const uint32_t*)&Bl[col][kk];
                uint32_t bl1 = *(const uint32_t*)&Bl[col][kk + 8];
                #pragma unroll
                for (int m = 0; m < 2; m++) {
                    mma_bf16(c[m][n], ah[m], bh0, bh1);
                    mma_bf16(c[m][n], ah[m], bl0, bl1);
                    mma_bf16(c[m][n], al[m], bh0, bh1);
                }
            }
        }
        __syncthreads();
    }

    // epilogue: c0/c1 at (row, 2lr), c2/c3 at (row+8, 2lr)
    if (blockIdx.y == 0) {
        #pragma unroll
        for (int m = 0; m < 2; m++) {
            int r1 = row0 + wm * 32 + m * 16 + lq;
            int r2 = r1 + 8;
            #pragma unroll
            for (int n = 0; n < 8; n++) {
                int col = wn * 64 + n * 8 + 2 * lr;
                if (r1 < NN)
                    *(__nv_bfloat162*)&g_y1lb[r1 * DD + col] =
                        __floats2bfloat162_rn(c[m][n][0], c[m][n][1]);
                if (r2 < NN)
                    *(__nv_bfloat162*)&g_y1lb[r2 * DD + col] =
                        __floats2bfloat162_rn(c[m][n][2], c[m][n][3]);
            }
        }
    } else {
        #pragma unroll
        for (int m = 0; m < 2; m++) {
            int r1 = row0 + wm * 32 + m * 16 + lq;
            int r2 = r1 + 8;
            #pragma unroll
            for (int n = 0; n < 8; n++) {
                int col = wn * 64 + n * 8 + 2 * lr;
                if (r1 < NN) *(float2*)&g_y1r[r1 * DD + col] = make_float2(c[m][n][0], c[m][n][1]);
                if (r2 < NN) *(float2*)&g_y1r[r2 * DD + col] = make_float2(c[m][n][2], c[m][n][3]);
            }
        }
    }
}

// -------- layer1 aggregate (bf16 gather, 4-deep MLP) + relu + l2 proj ------
__global__ void layer_kernel(const float* __restrict__ b1,
                             const float* __restrict__ W2l,
                             const float* __restrict__ W2r) {
    int warp = (blockIdx.x * blockDim.x + threadIdx.x) >> 5;
    int lane = threadIdx.x & 31;
    if (warp >= NN) return;
    int beg = g_off[warp], end = g_off[warp + 1];

    const uint2* yl = (const uint2*)g_y1lb;
    float a0 = 0.f, a1 = 0.f, a2 = 0.f, a3 = 0.f;
    int p = beg;
    // unrolled by 4: four independent index->gather chains in flight
    for (; p + 4 <= end; p += 4) {
        int s0 = g_srcs[p], s1 = g_srcs[p + 1];
        int s2 = g_srcs[p + 2], s3 = g_srcs[p + 3];
        uint2 v0 = yl[s0 * 32 + lane];
        uint2 v1 = yl[s1 * 32 + lane];
        uint2 v2 = yl[s2 * 32 + lane];
        uint2 v3 = yl[s3 * 32 + lane];
        float2 q;
        q = __bfloat1622float2(*(__nv_bfloat162*)&v0.x); a0 += q.x; a1 += q.y;
        q = __bfloat1622float2(*(__nv_bfloat162*)&v0.y); a2 += q.x; a3 += q.y;
        q = __bfloat1622float2(*(__nv_bfloat162*)&v1.x); a0 += q.x; a1 += q.y;
        q = __bfloat1622float2(*(__nv_bfloat162*)&v1.y); a2 += q.x; a3 += q.y;
        q = __bfloat1622float2(*(__nv_bfloat162*)&v2.x); a0 += q.x; a1 += q.y;
        q = __bfloat1622float2(*(__nv_bfloat162*)&v2.y); a2 += q.x; a3 += q.y;
        q = __bfloat1622float2(*(__nv_bfloat162*)&v3.x); a0 += q.x; a1 += q.y;
        q = __bfloat1622float2(*(__nv_bfloat162*)&v3.y); a2 += q.x; a3 += q.y;
    }
    for (; p < end; p++) {
        int s = g_srcs[p];
        uint2 v = yl[s * 32 + lane];
        float2 q;
        q = __bfloat1622float2(*(__nv_bfloat162*)&v.x); a0 += q.x; a1 += q.y;
        q = __bfloat1622float2(*(__nv_bfloat162*)&v.y); a2 += q.x; a3 += q.y;
    }
    float inv = 1.f / fmaxf((float)(end - beg), 1.f);
    float4 yr = ((const float4*)g_y1r)[warp * 32 + lane];
    float4 bb = ((const float4*)b1)[lane];
    float h0 = fmaxf(fmaf(a0, inv, bb.x + yr.x), 0.f);
    float h1 = fmaxf(fmaf(a1, inv, bb.y + yr.y), 0.f);
    float h2 = fmaxf(fmaf(a2, inv, bb.z + yr.z), 0.f);
    float h3 = fmaxf(fmaf(a3, inv, bb.w + yr.w), 0.f);

    float4 wl = ((const float4*)W2l)[lane];
    float4 wr = ((const float4*)W2r)[lane];
    float dl = h0 * wl.x + h1 * wl.y + h2 * wl.z + h3 * wl.w;
    float dr = h0 * wr.x + h1 * wr.y + h2 * wr.z + h3 * wr.w;
    #pragma unroll
    for (int o = 16; o; o >>= 1) {
        dl += __shfl_xor_sync(0xffffffffu, dl, o);
        dr += __shfl_xor_sync(0xffffffffu, dr, o);
    }
    if (lane == 0) { g_s[warp] = dl; g_t[warp] = dr; }
}

// -------- layer2 scalar aggregation + output (4-deep MLP) ----
__global__ void out_kernel(const float* __restrict__ b2, float* __restrict__ out) {
    int i = blockIdx.x * blockDim.x + threadIdx.x;
    if (i >= NN) return;
    int beg = g_off[i], end = g_off[i + 1];
    float s0 = 0.f, s1 = 0.f, s2 = 0.f, s3 = 0.f;
    int p = beg;
    for (; p + 4 <= end; p += 4) {
        int i0 = g_srcs[p], i1 = g_srcs[p + 1];
        int i2 = g_srcs[p + 2], i3 = g_srcs[p + 3];
        s0 += g_s[i0]; s1 += g_s[i1]; s2 += g_s[i2]; s3 += g_s[i3];
    }
    for (; p < end; p++) s0 += g_s[g_srcs[p]];
    float sum = (s0 + s1) + (s2 + s3);
    out[i] = sum / fmaxf((float)(end - beg), 1.f) + g_t[i] + b2[0];
}

// ---------------- launch: CSR chain forked onto a 2nd stream --------------
extern "C" void kernel_launch(void* const* d_in, const int* in_sizes, int n_in,
                              void* d_out, int out_size) {
    const float* x   = (const float*)d_in[0];
    const int*   ei  = (const int*)d_in[1];
    const float* W1l = (const float*)d_in[2];
    const float* b1  = (const float*)d_in[3];
    const float* W1r = (const float*)d_in[4];
    const float* W2l = (const float*)d_in[5];
    const float* b2  = (const float*)d_in[6];
    const float* W2r = (const float*)d_in[7];
    float* out = (float*)d_out;

    static cudaStream_t s2 = nullptr;
    static cudaEvent_t ev_fork = nullptr, ev_join = nullptr;
    if (!s2) {
        cudaStreamCreateWithFlags(&s2, cudaStreamNonBlocking);
        cudaEventCreateWithFlags(&ev_fork, cudaEventDisableTiming);
        cudaEventCreateWithFlags(&ev_join, cudaEventDisableTiming);
    }

    // fork: CSR chain on s2, GEMM chain on the main stream
    cudaEventRecord(ev_fork, 0);
    cudaStreamWaitEvent(s2, ev_fork, 0);

    zero_kernel <<<(NN + 255) / 256, 256, 0, s2>>>();
    count_kernel<<<(NE / 4 + 255) / 256, 256, 0, s2>>>(ei);
    scan1_kernel<<<NB1, 256, 0, s2>>>();
    scan23_kernel<<<NB1, 256, 0, s2>>>();
    fill_kernel <<<(NE / 4 + 255) / 256, 256, 0, s2>>>(ei);
    cudaEventRecord(ev_join, s2);

    conv_w_kernel<<<(DD * DD + 255) / 256, 256>>>(W1l, W1r);
    gemm_tc_kernel<<<dim3((NN + 127) / 128, 2), 256>>>(x);

    // join: layer needs both GEMM outputs and the CSR
    cudaStreamWaitEvent(0, ev_join, 0);
    layer_kernel<<<(NN * 32 + 255) / 256, 256>>>(b1, W2l, W2r);
    out_kernel<<<(NN + 255) / 256, 256>>>(b2, out);
}

// round 16
// speedup vs baseline: 1.0999x; 1.0999x over previous
#include <cuda_runtime.h>
#include <cuda_bf16.h>
#include <cstdint>

#define NN 50000
#define NE 600000
#define DD 128
#define NB1 ((NN + 255) / 256)     // 196 scan blocks

// ---------------- device scratch ----------------
__device__ __align__(16) __nv_bfloat16 g_y1lb[NN * DD];  // X @ W1_l (bf16, gathered)
__device__ __align__(16) float g_y1r[NN * DD];           // X @ W1_r (fp32, self term)
__device__ __align__(16) __nv_bfloat16 g_wbh[2 * DD * DD];  // W^T hi, [mat][n][k]
__device__ __align__(16) __nv_bfloat16 g_wbl[2 * DD * DD];  // W^T lo
__device__ __align__(16) float g_s[NN];          // h . W2_l
__device__ __align__(16) float g_t[NN];          // h . W2_r
__device__ __align__(16) int   g_deg[NN];
__device__ __align__(16) int   g_fill[NN];
__device__ __align__(16) int   g_incl[NN];
__device__ __align__(16) int   g_bsum[256];
__device__ __align__(16) int   g_off[NN + 2];
__device__ __align__(16) int   g_srcs[NE];

__device__ __forceinline__ int clampi(int v, int lo, int hi) {
    return v < lo ? lo : (v > hi ? hi : v);
}
__device__ __forceinline__ void mma_bf16(float* c, const uint32_t* a,
                                         uint32_t b0, uint32_t b1) {
    asm volatile(
        "mma.sync.aligned.m16n8k16.row.col.f32.bf16.bf16.f32 "
        "{%0,%1,%2,%3}, {%4,%5,%6,%7}, {%8,%9}, {%0,%1,%2,%3};"
        : "+f"(c[0]), "+f"(c[1]), "+f"(c[2]), "+f"(c[3])
        : "r"(a[0]), "r"(a[1]), "r"(a[2]), "r"(a[3]), "r"(b0), "r"(b1));
}

// ---------------- W hi/lo split + transpose: [k][n] -> [n][k] bf16 ----------
__global__ void conv_w_kernel(const float* __restrict__ Wl,
                              const float* __restrict__ Wr) {
    int i = blockIdx.x * blockDim.x + threadIdx.x;
    if (i >= DD * DD) return;
    int k = i >> 7, n = i & 127;
    float a = Wl[i], b = Wr[i];
    __nv_bfloat16 ah = __float2bfloat16_rn(a);
    __nv_bfloat16 bh = __float2bfloat16_rn(b);
    g_wbh[n * DD + k] = ah;
    g_wbl[n * DD + k] = __float2bfloat16_rn(a - __bfloat162float(ah));
    g_wbh[DD * DD + n * DD + k] = bh;
    g_wbl[DD * DD + n * DD + k] = __float2bfloat16_rn(b - __bfloat162float(bh));
}

// ---------------- CSR build ----------------
__global__ void zero_kernel() {
    int i = blockIdx.x * blockDim.x + threadIdx.x;
    if (i < NN) { g_deg[i] = 0; g_fill[i] = 0; }
}

__global__ void count_kernel(const int* __restrict__ ei) {
    int i = blockIdx.x * blockDim.x + threadIdx.x;
    if (i < NE / 4) {
        int4 d = ((const int4*)(ei + NE))[i];
        atomicAdd(&g_deg[clampi(d.x, 0, NN - 1)], 1);
        atomicAdd(&g_deg[clampi(d.y, 0, NN - 1)], 1);
        atomicAdd(&g_deg[clampi(d.z, 0, NN - 1)], 1);
        atomicAdd(&g_deg[clampi(d.w, 0, NN - 1)], 1);
    }
}

__global__ void scan1_kernel() {
    __shared__ int sh[256];
    int b = blockIdx.x, t = threadIdx.x, i = b * 256 + t;
    int v = (i < NN) ? g_deg[i] : 0;
    sh[t] = v;
    __syncthreads();
    #pragma unroll
    for (int ofs = 1; ofs < 256; ofs <<= 1) {
        int idx = (t >= ofs) ? (t - ofs) : t;
        int u = sh[idx];
        __syncthreads();
        if (t >= ofs) sh[t] += u;
        __syncthreads();
    }
    if (i < NN) g_incl[i] = sh[t];
    if (t == 255) g_bsum[b] = sh[255];
}

__global__ void scan23_kernel() {
    __shared__ int sh[256];
    int b = blockIdx.x, t = threadIdx.x;
    sh[t] = (t < b) ? g_bsum[t] : 0;
    __syncthreads();
    #pragma unroll
    for (int ofs = 128; ofs; ofs >>= 1) {
        if (t < ofs) sh[t] += sh[t + ofs];
        __syncthreads();
    }
    int boff = sh[0];
    int i = b * 256 + t;
    if (i < NN) g_off[i + 1] = g_incl[i] + boff;
    if (i == 0) g_off[0] = 0;
}

__global__ void fill_kernel(const int* __restrict__ ei) {
    int i = blockIdx.x * blockDim.x + threadIdx.x;
    if (i < NE / 4) {
        int4 s4 = ((const int4*)ei)[i];
        int4 d4 = ((const int4*)(ei + NE))[i];
        {
            int d = clampi(d4.x, 0, NN - 1);
            int pos = clampi(g_off[d] + atomicAdd(&g_fill[d], 1), 0, NE - 1);
            g_srcs[pos] = clampi(s4.x, 0, NN - 1);
        }
        {
            int d = clampi(d4.y, 0, NN - 1);
            int pos = clampi(g_off[d] + atomicAdd(&g_fill[d], 1), 0, NE - 1);
            g_srcs[pos] = clampi(s4.y, 0, NN - 1);
        }
        {
            int d = clampi(d4.z, 0, NN - 1);
            int pos = clampi(g_off[d] + atomicAdd(&g_fill[d], 1), 0, NE - 1);
            g_srcs[pos] = clampi(s4.z, 0, NN - 1);
        }
        {
            int d = clampi(d4.w, 0, NN - 1);
            int pos = clampi(g_off[d] + atomicAdd(&g_fill[d], 1), 0, NE - 1);
            g_srcs[pos] = clampi(s4.w, 0, NN - 1);
        }
    }
}

// ---------------- tensor-core GEMM (bf16 3-term split, fused conversion) ---
// Exactly the R9 best-measured version: in-register A cvt, int4 B staging,
// k-chunk 32, 8 warps of 32x64, m16n8k16. D = Xh*Wh + Xh*Wl + Xl*Wh.
#define APAD 40   // bf16 elems per row (32 + 8 pad) = 80 B
__global__ void __launch_bounds__(256, 2)
gemm_tc_kernel(const float* __restrict__ X) {
    __shared__ __nv_bfloat16 Ah[128][APAD], Al[128][APAD];
    __shared__ __nv_bfloat16 Bh[128][APAD], Bl[128][APAD];   // [col][k]

    const __nv_bfloat16* Wh = g_wbh + blockIdx.y * DD * DD;
    const __nv_bfloat16* Wl = g_wbl + blockIdx.y * DD * DD;

    int row0 = blockIdx.x * 128;
    int t = threadIdx.x, w = t >> 5, lane = t & 31;
    int wm = w & 3, wn = w >> 2;
    int lq = lane >> 2, lr = lane & 3;

    float c[2][8][4];
    #pragma unroll
    for (int m = 0; m < 2; m++)
        #pragma unroll
        for (int n = 0; n < 8; n++)
            #pragma unroll
            for (int j = 0; j < 4; j++) c[m][n][j] = 0.f;

    for (int kc = 0; kc < DD; kc += 32) {
        // stage A: 128 rows x 32 k; convert fp32 -> bf16 hi/lo in-register
        #pragma unroll
        for (int l = 0; l < 4; l++) {
            int s = t + 256 * l;                 // 0..1023 float4 slots
            int r = s >> 3, c4 = s & 7;
            int gr = row0 + r; gr = gr < NN ? gr : NN - 1;
            float4 v = *(const float4*)&X[gr * DD + kc + c4 * 4];
            __nv_bfloat16 hx = __float2bfloat16_rn(v.x);
            __nv_bfloat16 hy = __float2bfloat16_rn(v.y);
            __nv_bfloat16 hz = __float2bfloat16_rn(v.z);
            __nv_bfloat16 hw = __float2bfloat16_rn(v.w);
            Ah[r][c4 * 4 + 0] = hx; Ah[r][c4 * 4 + 1] = hy;
            Ah[r][c4 * 4 + 2] = hz; Ah[r][c4 * 4 + 3] = hw;
            Al[r][c4 * 4 + 0] = __float2bfloat16_rn(v.x - __bfloat162float(hx));
            Al[r][c4 * 4 + 1] = __float2bfloat16_rn(v.y - __bfloat162float(hy));
            Al[r][c4 * 4 + 2] = __float2bfloat16_rn(v.z - __bfloat162float(hz));
            Al[r][c4 * 4 + 3] = __float2bfloat16_rn(v.w - __bfloat162float(hw));
        }
        // stage B: pre-converted [col][k] bf16, pure int4 copy of k-slice
        #pragma unroll
        for (int l = 0; l < 2; l++) {
            int s = t + 256 * l;                 // 0..511 int4 slots
            int col = s >> 2, q = s & 3;
            *(int4*)&Bh[col][q * 8] = *(const int4*)&Wh[col * DD + kc + q * 8];
            *(int4*)&Bl[col][q * 8] = *(const int4*)&Wl[col * DD + kc + q * 8];
        }
        __syncthreads();

        #pragma unroll
        for (int k0 = 0; k0 < 32; k0 += 16) {
            uint32_t ah[2][4], al[2][4];
            #pragma unroll
            for (int m = 0; m < 2; m++) {
                int r = wm * 32 + m * 16 + lq;
                int kk = k0 + 2 * lr;
                ah[m][0] = *(const uint32_t*)&Ah[r][kk];
                ah[m][1] = *(const uint32_t*)&Ah[r + 8][kk];
                ah[m][2] = *(const uint32_t*)&Ah[r][kk + 8];
                ah[m][3] = *(const uint32_t*)&Ah[r + 8][kk + 8];
                al[m][0] = *(const uint32_t*)&Al[r][kk];
                al[m][1] = *(const uint32_t*)&Al[r + 8][kk];
                al[m][2] = *(const uint32_t*)&Al[r][kk + 8];
                al[m][3] = *(const uint32_t*)&Al[r + 8][kk + 8];
            }
            #pragma unroll
            for (int n = 0; n < 8; n++) {
                int col = wn * 64 + n * 8 + lq;
                int kk = k0 + 2 * lr;
                uint32_t bh0 = *(const uint32_t*)&Bh[col][kk];
                uint32_t bh1 = *(const uint32_t*)&Bh[col][kk + 8];
                uint32_t bl0 = *(const uint32_t*)&Bl[col][kk];
                uint32_t bl1 = *(const uint32_t*)&Bl[col][kk + 8];
                #pragma unroll
                for (int m = 0; m < 2; m++) {
                    mma_bf16(c[m][n], ah[m], bh0, bh1);
                    mma_bf16(c[m][n], ah[m], bl0, bl1);
                    mma_bf16(c[m][n], al[m], bh0, bh1);
                }
            }
        }
        __syncthreads();
    }

    // epilogue: c0/c1 at (row, 2lr), c2/c3 at (row+8, 2lr)
    if (blockIdx.y == 0) {
        #pragma unroll
        for (int m = 0; m < 2; m++) {
            int r1 = row0 + wm * 32 + m * 16 + lq;
            int r2 = r1 + 8;
            #pragma unroll
            for (int n = 0; n < 8; n++) {
                int col = wn * 64 + n * 8 + 2 * lr;
                if (r1 < NN)
                    *(__nv_bfloat162*)&g_y1lb[r1 * DD + col] =
                        __floats2bfloat162_rn(c[m][n][0], c[m][n][1]);
                if (r2 < NN)
                    *(__nv_bfloat162*)&g_y1lb[r2 * DD + col] =
                        __floats2bfloat162_rn(c[m][n][2], c[m][n][3]);
            }
        }
    } else {
        #pragma unroll
        for (int m = 0; m < 2; m++) {
            int r1 = row0 + wm * 32 + m * 16 + lq;
            int r2 = r1 + 8;
            #pragma unroll
            for (int n = 0; n < 8; n++) {
                int col = wn * 64 + n * 8 + 2 * lr;
                if (r1 < NN) *(float2*)&g_y1r[r1 * DD + col] = make_float2(c[m][n][0], c[m][n][1]);
                if (r2 < NN) *(float2*)&g_y1r[r2 * DD + col] = make_float2(c[m][n][2], c[m][n][3]);
            }
        }
    }
}

// -------- layer1 aggregate (bf16 gather) + relu + fused layer2 proj --------
__global__ void layer_kernel(const float* __restrict__ b1,
                             const float* __restrict__ W2l,
                             const float* __restrict__ W2r) {
    int warp = (blockIdx.x * blockDim.x + threadIdx.x) >> 5;
    int lane = threadIdx.x & 31;
    if (warp >= NN) return;
    int beg = g_off[warp], end = g_off[warp + 1];

    const uint2* yl = (const uint2*)g_y1lb;
    float a0 = 0.f, a1 = 0.f, a2 = 0.f, a3 = 0.f;
    for (int p = beg; p < end; p++) {
        int s = g_srcs[p];
        uint2 v = yl[s * 32 + lane];
        float2 p0 = __bfloat1622float2(*(__nv_bfloat162*)&v.x);
        float2 p1 = __bfloat1622float2(*(__nv_bfloat162*)&v.y);
        a0 += p0.x; a1 += p0.y; a2 += p1.x; a3 += p1.y;
    }
    float inv = 1.f / fmaxf((float)(end - beg), 1.f);
    float4 yr = ((const float4*)g_y1r)[warp * 32 + lane];
    float4 bb = ((const float4*)b1)[lane];
    float h0 = fmaxf(fmaf(a0, inv, bb.x + yr.x), 0.f);
    float h1 = fmaxf(fmaf(a1, inv, bb.y + yr.y), 0.f);
    float h2 = fmaxf(fmaf(a2, inv, bb.z + yr.z), 0.f);
    float h3 = fmaxf(fmaf(a3, inv, bb.w + yr.w), 0.f);

    float4 wl = ((const float4*)W2l)[lane];
    float4 wr = ((const float4*)W2r)[lane];
    float dl = h0 * wl.x + h1 * wl.y + h2 * wl.z + h3 * wl.w;
    float dr = h0 * wr.x + h1 * wr.y + h2 * wr.z + h3 * wr.w;
    #pragma unroll
    for (int o = 16; o; o >>= 1) {
        dl += __shfl_xor_sync(0xffffffffu, dl, o);
        dr += __shfl_xor_sync(0xffffffffu, dr, o);
    }
    if (lane == 0) { g_s[warp] = dl; g_t[warp] = dr; }
}

// -------- layer2 scalar aggregation + output ----
__global__ void out_kernel(const float* __restrict__ b2, float* __restrict__ out) {
    int i = blockIdx.x * blockDim.x + threadIdx.x;
    if (i >= NN) return;
    int beg = g_off[i], end = g_off[i + 1];
    float sum = 0.f;
    for (int p = beg; p < end; p++) sum += g_s[g_srcs[p]];
    out[i] = sum / fmaxf((float)(end - beg), 1.f) + g_t[i] + b2[0];
}

// ---------------- launch: same dependencies as R9, submission order puts
// gemm at launch #6 so ncu (-s 5 -c 1) finally profiles the GEMM ------------
extern "C" void kernel_launch(void* const* d_in, const int* in_sizes, int n_in,
                              void* d_out, int out_size) {
    const float* x   = (const float*)d_in[0];
    const int*   ei  = (const int*)d_in[1];
    const float* W1l = (const float*)d_in[2];
    const float* b1  = (const float*)d_in[3];
    const float* W1r = (const float*)d_in[4];
    const float* W2l = (const float*)d_in[5];
    const float* b2  = (const float*)d_in[6];
    const float* W2r = (const float*)d_in[7];
    float* out = (float*)d_out;

    static cudaStream_t s2 = nullptr;
    static cudaEvent_t ev_fork = nullptr, ev_join = nullptr;
    if (!s2) {
        cudaStreamCreateWithFlags(&s2, cudaStreamNonBlocking);
        cudaEventCreateWithFlags(&ev_fork, cudaEventDisableTiming);
        cudaEventCreateWithFlags(&ev_join, cudaEventDisableTiming);
    }

    cudaEventRecord(ev_fork, 0);
    cudaStreamWaitEvent(s2, ev_fork, 0);

    conv_w_kernel<<<(DD * DD + 255) / 256, 256>>>(W1l, W1r);           // #1 (main)
    zero_kernel <<<(NN + 255) / 256, 256, 0, s2>>>();                  // #2 (s2)
    count_kernel<<<(NE / 4 + 255) / 256, 256, 0, s2>>>(ei);            // #3 (s2)
    scan1_kernel<<<NB1, 256, 0, s2>>>();                               // #4 (s2)
    scan23_kernel<<<NB1, 256, 0, s2>>>();                              // #5 (s2)
    gemm_tc_kernel<<<dim3((NN + 127) / 128, 2), 256>>>(x);             // #6 (main) <- profiled
    fill_kernel <<<(NE / 4 + 255) / 256, 256, 0, s2>>>(ei);            // #7 (s2)
    cudaEventRecord(ev_join, s2);

    cudaStreamWaitEvent(0, ev_join, 0);
    layer_kernel<<<(NN * 32 + 255) / 256, 256>>>(b1, W2l, W2r);        // #8 (main)
    out_kernel<<<(NN + 255) / 256, 256>>>(b2, out);                    // #9 (main)
}